// round 11
// baseline (speedup 1.0000x reference)
#include <cuda_runtime.h>
#include <cstdint>

// Problem constants
constexpr int Bc  = 2;
constexpr int Sc  = 2048;
constexpr int Dc  = 1024;
constexpr int Hc  = 16;
constexpr int HDc = 64;
constexpr int Nrows = Bc * Sc;                       // 4096
constexpr long OUT_ELEMS = (long)Bc * Sc * Dc;       // 4,194,304

// Scratch (device globals; sanctioned mechanism).
__device__ __align__(16) float g_Q[Bc * Hc * Sc * HDc];    // [B,H,S,HD], pre-scaled by 1/8
__device__ __align__(16) float g_K[Bc * Hc * Sc * HDc];
__device__ __align__(16) float g_V[Bc * Hc * Sc * HDc];
__device__ __align__(16) float g_ctx[(long)Nrows * Dc];    // [B*S, D]
__device__ __align__(16) float g_invl[Bc * Hc * Sc];       // 1/rowsum per (bh,q)

// ---------------------------------------------------------------------------
// helpers
// ---------------------------------------------------------------------------
__device__ __forceinline__ float stf(float x) {
    uint32_t r;
    asm("cvt.rna.tf32.f32 %0, %1;" : "=r"(r) : "f"(x));
    return __uint_as_float(r);
}

__device__ __forceinline__ void mma8(float4& d, float4 a, float2 b)
{
    asm volatile(
        "mma.sync.aligned.m16n8k8.row.col.f32.tf32.tf32.f32 "
        "{%0,%1,%2,%3}, {%4,%5,%6,%7}, {%8,%9}, {%0,%1,%2,%3};"
        : "+f"(d.x), "+f"(d.y), "+f"(d.z), "+f"(d.w)
        : "r"(__float_as_uint(a.x)), "r"(__float_as_uint(a.y)),
          "r"(__float_as_uint(a.z)), "r"(__float_as_uint(a.w)),
          "r"(__float_as_uint(b.x)), "r"(__float_as_uint(b.y)));
}

__device__ __forceinline__ void cpa16(uint32_t dst, const float* src) {
    asm volatile("cp.async.cg.shared.global [%0], [%1], 16;" :: "r"(dst), "l"(src));
}

// ---------------------------------------------------------------------------
// QKV projection GEMM with cp.async 2-stage pipeline. 128x128 tile, BK=16,
// 256 thr, 8 warps (4m x 2n). Row-major smem stride 20. Consume-time tf32.
// Scatters C to [B,H,S,HD]; dst 0/1/2 = Q/K/V.
// ---------------------------------------------------------------------------
__global__ __launch_bounds__(256) void k_gemm1024(
    const float* __restrict__ Ain, const float* __restrict__ W,
    const float* __restrict__ bias, int dst, float scale)
{
    __shared__ float As[2][128 * 20];
    __shared__ float Ws[2][128 * 20];

    float* C = (dst == 0) ? g_Q : (dst == 1) ? g_K : g_V;

    const int row0 = blockIdx.y * 128, col0 = blockIdx.x * 128;
    const int t = threadIdx.x, wid = t >> 5, lane = t & 31;
    const int grp = lane >> 2, tig = lane & 3;
    const int wm = (wid >> 1) * 32, wn = (wid & 1) * 64;
    const int sr = t >> 1, sc8 = (t & 1) * 8;

    const float* Ap = Ain + (long)(row0 + sr) * Dc + sc8;
    const float* Wp = W   + (long)(col0 + sr) * Dc + sc8;

    const uint32_t aSm = (uint32_t)__cvta_generic_to_shared(&As[0][sr * 20 + sc8]);
    const uint32_t wSm = (uint32_t)__cvta_generic_to_shared(&Ws[0][sr * 20 + sc8]);
    constexpr uint32_t BUFB = 128 * 20 * 4;

    float4 acc0[8], acc1[8];
#pragma unroll
    for (int i = 0; i < 8; i++) {
        acc0[i] = make_float4(0.f, 0.f, 0.f, 0.f);
        acc1[i] = make_float4(0.f, 0.f, 0.f, 0.f);
    }

    cpa16(aSm, Ap); cpa16(aSm + 16, Ap + 4);
    cpa16(wSm, Wp); cpa16(wSm + 16, Wp + 4);
    asm volatile("cp.async.commit_group;");

    for (int kt = 0; kt < 64; kt++) {
        if (kt < 63) {
            const int k0 = (kt + 1) * 16;
            const uint32_t b = ((kt + 1) & 1) * BUFB;
            cpa16(aSm + b, Ap + k0); cpa16(aSm + b + 16, Ap + k0 + 4);
            cpa16(wSm + b, Wp + k0); cpa16(wSm + b + 16, Wp + k0 + 4);
            asm volatile("cp.async.commit_group;");
            asm volatile("cp.async.wait_group 1;");
        } else {
            asm volatile("cp.async.wait_group 0;");
        }
        __syncthreads();

        const float* Ab = As[kt & 1];
        const float* Wb = Ws[kt & 1];
#pragma unroll
        for (int kb = 0; kb < 2; kb++) {
            const int ko = kb * 8 + tig;
            float4 fa0 = make_float4(stf(Ab[(wm + grp     ) * 20 + ko]),
                                     stf(Ab[(wm + grp + 8 ) * 20 + ko]),
                                     stf(Ab[(wm + grp     ) * 20 + ko + 4]),
                                     stf(Ab[(wm + grp + 8 ) * 20 + ko + 4]));
            float4 fa1 = make_float4(stf(Ab[(wm + 16 + grp    ) * 20 + ko]),
                                     stf(Ab[(wm + 16 + grp + 8) * 20 + ko]),
                                     stf(Ab[(wm + 16 + grp    ) * 20 + ko + 4]),
                                     stf(Ab[(wm + 16 + grp + 8) * 20 + ko + 4]));
#pragma unroll
            for (int j = 0; j < 8; j++) {
                float2 fb = make_float2(stf(Wb[(wn + j * 8 + grp) * 20 + ko]),
                                        stf(Wb[(wn + j * 8 + grp) * 20 + ko + 4]));
                mma8(acc0[j], fa0, fb);
                mma8(acc1[j], fa1, fb);
            }
        }
        __syncthreads();
    }

#pragma unroll
    for (int mt = 0; mt < 2; mt++) {
#pragma unroll
        for (int j = 0; j < 8; j++) {
            float4 c = mt ? acc1[j] : acc0[j];
            const int row = row0 + wm + mt * 16 + grp;
            const int col = col0 + wn + j * 8 + tig * 2;
            const float bx0 = bias[col], bx1 = bias[col + 1];
            const int h = col >> 6, hd = col & 63;
            {
                const int bb = row >> 11, s = row & 2047;
                *(float2*)&C[(((long)(bb * Hc + h)) * Sc + s) * HDc + hd] =
                    make_float2((c.x + bx0) * scale, (c.y + bx1) * scale);
            }
            {
                const int r2 = row + 8;
                const int bb = r2 >> 11, s = r2 & 2047;
                *(float2*)&C[(((long)(bb * Hc + h)) * Sc + s) * HDc + hd] =
                    make_float2((c.z + bx0) * scale, (c.w + bx1) * scale);
            }
        }
    }
}

// ---------------------------------------------------------------------------
// Combined output projection + attn rescale (independent workloads, one
// launch so rescale's DRAM streaming hides under oproj's latency-bound GEMM).
// CTAs [0,256): out = g_ctx @ Wo^T + bo (cp.async pipeline, row-major).
// CTAs [256, 256+B*H*S): scale attn row (blockIdx.x-256) by g_invl.
// ---------------------------------------------------------------------------
__global__ __launch_bounds__(256) void k_oproj_rescale(
    const float* __restrict__ W, const float* __restrict__ bias,
    float* __restrict__ out, float* __restrict__ ATT)
{
    __shared__ float As[2][128 * 20];
    __shared__ float Ws[2][128 * 20];

    if (blockIdx.x >= 256) {
        // ---- rescale part ----
        const long row = blockIdx.x - 256;
        const int  q   = (int)(row & (Sc - 1));
        const float il = g_invl[row];
        float* p = ATT + row * Sc;
        const int nc = (((q >> 7) + 1) << 7);   // cols written by fused kernel
        const int t4 = threadIdx.x * 4;
        for (int i = t4; i < nc; i += 1024) {
            float4 v = *(float4*)&p[i];
            v.x *= il; v.y *= il; v.z *= il; v.w *= il;
            *(float4*)&p[i] = v;
        }
        return;
    }

    // ---- oproj part ----
    const int bx = blockIdx.x;
    const int row0 = (bx >> 3) * 128, col0 = (bx & 7) * 128;
    const int t = threadIdx.x, wid = t >> 5, lane = t & 31;
    const int grp = lane >> 2, tig = lane & 3;
    const int wm = (wid >> 1) * 32, wn = (wid & 1) * 64;
    const int sr = t >> 1, sc8 = (t & 1) * 8;

    const float* Ap = g_ctx + (long)(row0 + sr) * Dc + sc8;
    const float* Wp = W     + (long)(col0 + sr) * Dc + sc8;

    const uint32_t aSm = (uint32_t)__cvta_generic_to_shared(&As[0][sr * 20 + sc8]);
    const uint32_t wSm = (uint32_t)__cvta_generic_to_shared(&Ws[0][sr * 20 + sc8]);
    constexpr uint32_t BUFB = 128 * 20 * 4;

    float4 acc0[8], acc1[8];
#pragma unroll
    for (int i = 0; i < 8; i++) {
        acc0[i] = make_float4(0.f, 0.f, 0.f, 0.f);
        acc1[i] = make_float4(0.f, 0.f, 0.f, 0.f);
    }

    cpa16(aSm, Ap); cpa16(aSm + 16, Ap + 4);
    cpa16(wSm, Wp); cpa16(wSm + 16, Wp + 4);
    asm volatile("cp.async.commit_group;");

    for (int kt = 0; kt < 64; kt++) {
        if (kt < 63) {
            const int k0 = (kt + 1) * 16;
            const uint32_t b = ((kt + 1) & 1) * BUFB;
            cpa16(aSm + b, Ap + k0); cpa16(aSm + b + 16, Ap + k0 + 4);
            cpa16(wSm + b, Wp + k0); cpa16(wSm + b + 16, Wp + k0 + 4);
            asm volatile("cp.async.commit_group;");
            asm volatile("cp.async.wait_group 1;");
        } else {
            asm volatile("cp.async.wait_group 0;");
        }
        __syncthreads();

        const float* Ab = As[kt & 1];
        const float* Wb = Ws[kt & 1];
#pragma unroll
        for (int kb = 0; kb < 2; kb++) {
            const int ko = kb * 8 + tig;
            float4 fa0 = make_float4(stf(Ab[(wm + grp     ) * 20 + ko]),
                                     stf(Ab[(wm + grp + 8 ) * 20 + ko]),
                                     stf(Ab[(wm + grp     ) * 20 + ko + 4]),
                                     stf(Ab[(wm + grp + 8 ) * 20 + ko + 4]));
            float4 fa1 = make_float4(stf(Ab[(wm + 16 + grp    ) * 20 + ko]),
                                     stf(Ab[(wm + 16 + grp + 8) * 20 + ko]),
                                     stf(Ab[(wm + 16 + grp    ) * 20 + ko + 4]),
                                     stf(Ab[(wm + 16 + grp + 8) * 20 + ko + 4]));
#pragma unroll
            for (int j = 0; j < 8; j++) {
                float2 fb = make_float2(stf(Wb[(wn + j * 8 + grp) * 20 + ko]),
                                        stf(Wb[(wn + j * 8 + grp) * 20 + ko + 4]));
                mma8(acc0[j], fa0, fb);
                mma8(acc1[j], fa1, fb);
            }
        }
        __syncthreads();
    }

#pragma unroll
    for (int mt = 0; mt < 2; mt++) {
#pragma unroll
        for (int j = 0; j < 8; j++) {
            float4 c = mt ? acc1[j] : acc0[j];
            const int row = row0 + wm + mt * 16 + grp;
            const int col = col0 + wn + j * 8 + tig * 2;
            const float bx0 = bias[col], bx1 = bias[col + 1];
            *(float2*)&out[(long)row * Dc + col] =
                make_float2(c.x + bx0, c.y + bx1);
            *(float2*)&out[(long)(row + 8) * Dc + col] =
                make_float2(c.z + bx0, c.w + bx1);
        }
    }
}

// ---------------------------------------------------------------------------
// Fused causal attention, SINGLE PASS, 512 threads (16 warps), with
// REGISTER PREFETCH of K/V (loads for tile kt+1 issued after the S-epilogue,
// consumed at the next iteration's staging — latency hidden by PV-mma).
// Per k-tile: S = QK^T, e = exp(s) masked -> UNNORMALIZED to ATT + P frags,
// row sums accumulated, O += P@V. Epilogue: O *= 1/l, 1/l -> g_invl.
// Zero-fills the attn upper triangle. Fragment-major smem (~170 KB).
// ---------------------------------------------------------------------------
__global__ __launch_bounds__(512) void k_attn_fused(float* __restrict__ ATT)
{
    extern __shared__ float smf[];
    float* QsF  = smf;                 // 8448  [mt8][kb8]*132
    float* KsF  = smf + 8448;          // 8704  [nt16][kb8]*68
    float* VsF  = KsF + 8704;          // 8704  [kb16][nt8]*68
    float* PsF  = VsF + 8704;          // 16896 [mt8][kb16]*132
    float* red  = PsF + 16896;         // 512
    float* invl = red + 512;           // 128

    const int bh = blockIdx.z;
    const int qt = (int)gridDim.x - 1 - (int)blockIdx.x;   // heavy tiles first
    const int q0 = qt * 128;
    const float* Qg = g_Q + (long)bh * Sc * HDc;
    const float* Kg = g_K + (long)bh * Sc * HDc;
    const float* Vg = g_V + (long)bh * Sc * HDc;
    float* Ab = ATT + (long)bh * Sc * Sc;

    const int t = threadIdx.x, wid = t >> 5, lane = t & 31;
    const int grp = lane >> 2, tig = lane & 3;
    const int wm   = (wid >> 2) * 32;
    const int mt0  = (wid >> 2) * 2;
    const int wqS  = wid & 3;
    const int ntS0 = wqS * 4;
    const int ntO0 = (wid & 3) * 2;

    // staging coordinates (fixed per thread)
    const int sRow = t >> 4, sC4 = (t & 15) * 4;    // +128 per i via idx

    // prologue: prefetch K/V tile 0 into registers (overlaps fills below)
    float4 kR[4], vR[4];
#pragma unroll
    for (int i = 0; i < 4; i++) {
        const int row = (t + i * 512) >> 4;
        const int c4  = ((t + i * 512) & 15) * 4;
        kR[i] = *(const float4*)(Kg + (long)row * HDc + c4);
        vR[i] = *(const float4*)(Vg + (long)row * HDc + c4);
    }

    // Zero-fill attn cols [q0+128, Sc)  (rides the idle DRAM pipe)
    {
        const int W = Sc - q0 - 128;
        if (W > 0) {
            const int w4 = W >> 2;
            const int tot = 128 * w4;
            for (int idx = t; idx < tot; idx += 512) {
                const int row = idx / w4;
                const int cw  = (idx - row * w4) * 4;
                *(float4*)&Ab[(long)(q0 + row) * Sc + q0 + 128 + cw] =
                    make_float4(0.f, 0.f, 0.f, 0.f);
            }
        }
    }

    // Stage Q tile (128x64) as A-fragments
#pragma unroll
    for (int i = 0; i < 4; i++) {
        const int idx = t + i * 512;
        const int row = idx >> 4, c4 = (idx & 15) * 4;
        float4 v = *(const float4*)(Qg + (long)(q0 + row) * HDc + c4);
        const int kb = c4 >> 3, k4 = (c4 >> 2) & 1;
        const int mt = row >> 4, m = row & 15;
        const int b = (mt * 8 + kb) * 132 + (m & 7) * 16 + k4 * 2 + ((m >> 3) & 1);
        QsF[b + 0] = stf(v.x); QsF[b + 4]  = stf(v.y);
        QsF[b + 8] = stf(v.z); QsF[b + 12] = stf(v.w);
    }

    float ps00 = 0.f, ps01 = 0.f, ps10 = 0.f, ps11 = 0.f;
    float4 o0[2], o1[2];
#pragma unroll
    for (int i = 0; i < 2; i++) {
        o0[i] = make_float4(0.f, 0.f, 0.f, 0.f);
        o1[i] = make_float4(0.f, 0.f, 0.f, 0.f);
    }

    for (int kt = 0; kt <= qt; kt++) {
        __syncthreads();   // prev PV done (and Q staging / prologue first iter)

        // stage K/V from prefetch registers (formatted, tf32)
#pragma unroll
        for (int i = 0; i < 4; i++) {
            const int idx = t + i * 512;
            const int row = idx >> 4, c4 = (idx & 15) * 4;
            float4 kv = kR[i];
            {
                const int kb = c4 >> 3, k4 = (c4 >> 2) & 1;
                const int nt = row >> 3, n = row & 7;
                const int b = (nt * 8 + kb) * 68 + n * 8 + k4;
                KsF[b + 0] = stf(kv.x); KsF[b + 2] = stf(kv.y);
                KsF[b + 4] = stf(kv.z); KsF[b + 6] = stf(kv.w);
            }
            float4 vv = vR[i];
            {
                const int kbv = row >> 3, kk = row & 7;
                const int nt = c4 >> 3, nb = c4 & 7;
                const int b = (kbv * 8 + nt) * 68 + nb * 8 + (kk & 3) * 2 + ((kk >> 2) & 1);
                VsF[b + 0]  = stf(vv.x); VsF[b + 8]  = stf(vv.y);
                VsF[b + 16] = stf(vv.z); VsF[b + 24] = stf(vv.w);
            }
        }
        __syncthreads();

        // S = Q @ K^T
        float4 acc0[4], acc1[4];
#pragma unroll
        for (int i = 0; i < 4; i++) {
            acc0[i] = make_float4(0.f, 0.f, 0.f, 0.f);
            acc1[i] = make_float4(0.f, 0.f, 0.f, 0.f);
        }
#pragma unroll
        for (int kb = 0; kb < 8; kb++) {
            float4 fa0 = *(const float4*)&QsF[((mt0 + 0) * 8 + kb) * 132 + lane * 4];
            float4 fa1 = *(const float4*)&QsF[((mt0 + 1) * 8 + kb) * 132 + lane * 4];
#pragma unroll
            for (int j = 0; j < 4; j++) {
                float2 fb = *(const float2*)&KsF[((ntS0 + j) * 8 + kb) * 68 + lane * 2];
                mma8(acc0[j], fa0, fb);
                mma8(acc1[j], fa1, fb);
            }
        }

        // exp (unnormalized), mask, write ATT, stage P frags, accumulate sums
        const bool diag = (kt == qt);
#pragma unroll
        for (int mt = 0; mt < 2; mt++) {
            const int r = wm + mt * 16 + grp;
            const int mtg = mt0 + mt;
#pragma unroll
            for (int j = 0; j < 4; j++) {
                float4 c = mt ? acc1[j] : acc0[j];
                const int cc = wqS * 32 + j * 8 + tig * 2;
                float ex = (!diag || cc     <= r    ) ? __expf(c.x) : 0.f;
                float ey = (!diag || cc + 1 <= r    ) ? __expf(c.y) : 0.f;
                float ez = (!diag || cc     <= r + 8) ? __expf(c.z) : 0.f;
                float ew = (!diag || cc + 1 <= r + 8) ? __expf(c.w) : 0.f;
                if (mt == 0) { ps00 += ex + ey; ps01 += ez + ew; }
                else         { ps10 += ex + ey; ps11 += ez + ew; }
                const long gr = (long)(q0 + r) * Sc + kt * 128 + cc;
                *(float2*)&Ab[gr]          = make_float2(ex, ey);
                *(float2*)&Ab[gr + 8 * Sc] = make_float2(ez, ew);
                const int kbp = wqS * 4 + j;
                const int k = tig * 2;
                const int o = (mtg * 16 + kbp) * 132 + grp * 16 + (k & 3) * 4 + (k >> 2) * 2;
                *(float2*)&PsF[o]     = make_float2(stf(ex), stf(ez));
                *(float2*)&PsF[o + 4] = make_float2(stf(ey), stf(ew));
            }
        }

        // prefetch K/V tile kt+1 (latency hidden by barrier + PV-mma)
        if (kt < qt) {
#pragma unroll
            for (int i = 0; i < 4; i++) {
                const int row = (t + i * 512) >> 4;
                const int c4  = ((t + i * 512) & 15) * 4;
                kR[i] = *(const float4*)(Kg + (long)((kt + 1) * 128 + row) * HDc + c4);
                vR[i] = *(const float4*)(Vg + (long)((kt + 1) * 128 + row) * HDc + c4);
            }
        }
        __syncthreads();

        // O += P @ V
#pragma unroll
        for (int kb = 0; kb < 16; kb++) {
            float4 pa0 = *(const float4*)&PsF[((mt0 + 0) * 16 + kb) * 132 + lane * 4];
            float4 pa1 = *(const float4*)&PsF[((mt0 + 1) * 16 + kb) * 132 + lane * 4];
#pragma unroll
            for (int j = 0; j < 2; j++) {
                float2 vb = *(const float2*)&VsF[(kb * 8 + ntO0 + j) * 68 + lane * 2];
                mma8(o0[j], pa0, vb);
                mma8(o1[j], pa1, vb);
            }
        }
    }

    // row-sum reduction -> invl
#pragma unroll
    for (int o = 1; o <= 2; o <<= 1) {
        ps00 += __shfl_xor_sync(0xffffffffu, ps00, o);
        ps01 += __shfl_xor_sync(0xffffffffu, ps01, o);
        ps10 += __shfl_xor_sync(0xffffffffu, ps10, o);
        ps11 += __shfl_xor_sync(0xffffffffu, ps11, o);
    }
    if (tig == 0) {
        float* rb = red + wqS * 128;
        rb[wm + grp]          = ps00;
        rb[wm + grp + 8]      = ps01;
        rb[wm + 16 + grp]     = ps10;
        rb[wm + 16 + grp + 8] = ps11;
    }
    __syncthreads();
    if (t < 128) {
        const float il = 1.0f / (red[t] + red[128 + t] + red[256 + t] + red[384 + t]);
        invl[t] = il;
        g_invl[(long)bh * Sc + q0 + t] = il;
    }
    __syncthreads();

    // epilogue: ctx = O * invl
    const int bb = bh >> 4, h = bh & 15;
#pragma unroll
    for (int mt = 0; mt < 2; mt++) {
        const int r = wm + mt * 16 + grp;
        const float il0 = invl[r], il1 = invl[r + 8];
#pragma unroll
        for (int j = 0; j < 2; j++) {
            float4 c = mt ? o1[j] : o0[j];
            const int gq  = q0 + r;
            const int col = (wid & 3) * 16 + j * 8 + tig * 2;
            *(float2*)&g_ctx[((long)bb * Sc + gq) * Dc + h * HDc + col] =
                make_float2(c.x * il0, c.y * il0);
            *(float2*)&g_ctx[((long)bb * Sc + gq + 8) * Dc + h * HDc + col] =
                make_float2(c.z * il1, c.w * il1);
        }
    }
}

// ---------------------------------------------------------------------------
// kernel_launch
// Inputs: 0 query, 1 key, 2 value, 3 mask, 4 Wq, 5 bq, 6 Wk, 7 bk,
//         8 Wv, 9 bv, 10 Wo, 11 bo
// Output tuple (output, attn): out[0:B*S*D], attn at out + B*S*D.
// ---------------------------------------------------------------------------
extern "C" void kernel_launch(void* const* d_in, const int* in_sizes, int n_in,
                              void* d_out, int out_size)
{
    const float* query = (const float*)d_in[0];
    const float* key_  = (const float*)d_in[1];
    const float* value = (const float*)d_in[2];
    const float* Wq = (const float*)d_in[4];
    const float* bq = (const float*)d_in[5];
    const float* Wk = (const float*)d_in[6];
    const float* bk = (const float*)d_in[7];
    const float* Wv = (const float*)d_in[8];
    const float* bv = (const float*)d_in[9];
    const float* Wo = (const float*)d_in[10];
    const float* bo = (const float*)d_in[11];
    float* out = (float*)d_out;

    float* ATT = out + OUT_ELEMS;   // attn region of the output tuple

    constexpr int FUSED_SMEM = (8448 + 8704 + 8704 + 16896 + 512 + 128) * 4;
    cudaFuncSetAttribute(k_attn_fused,
                         cudaFuncAttributeMaxDynamicSharedMemorySize, FUSED_SMEM);

    const dim3 blk(256);

    k_gemm1024<<<dim3(Dc / 128, Nrows / 128), blk>>>(query, Wq, bq, 0, 0.125f);
    k_gemm1024<<<dim3(Dc / 128, Nrows / 128), blk>>>(key_,  Wk, bk, 1, 1.0f);
    k_gemm1024<<<dim3(Dc / 128, Nrows / 128), blk>>>(value, Wv, bv, 2, 1.0f);

    k_attn_fused<<<dim3(Sc / 128, 1, Bc * Hc), dim3(512), FUSED_SMEM>>>(ATT);

    // combined: oproj (CTAs 0..255) + attn rescale (CTAs 256..256+B*H*S-1)
    k_oproj_rescale<<<dim3(256 + Bc * Hc * Sc), blk>>>(Wo, bo, out, ATT);
}

// round 14
// speedup vs baseline: 1.2247x; 1.2247x over previous
#include <cuda_runtime.h>
#include <cstdint>

// Problem constants
constexpr int Bc  = 2;
constexpr int Sc  = 2048;
constexpr int Dc  = 1024;
constexpr int Hc  = 16;
constexpr int HDc = 64;
constexpr int Nrows = Bc * Sc;                       // 4096
constexpr long OUT_ELEMS = (long)Bc * Sc * Dc;       // 4,194,304

// Scratch (device globals; sanctioned mechanism).
__device__ __align__(16) float g_Q[Bc * Hc * Sc * HDc];    // [B,H,S,HD], pre-scaled by 1/8
__device__ __align__(16) float g_K[Bc * Hc * Sc * HDc];
__device__ __align__(16) float g_V[Bc * Hc * Sc * HDc];
__device__ __align__(16) float g_ctx[(long)Nrows * Dc];    // [B*S, D]
__device__ __align__(16) float g_invl[Bc * Hc * Sc];       // 1/rowsum per (bh,q)

// ---------------------------------------------------------------------------
// helpers
// ---------------------------------------------------------------------------
__device__ __forceinline__ float stf(float x) {
    uint32_t r;
    asm("cvt.rna.tf32.f32 %0, %1;" : "=r"(r) : "f"(x));
    return __uint_as_float(r);
}

__device__ __forceinline__ void mma8(float4& d, float4 a, float2 b)
{
    asm volatile(
        "mma.sync.aligned.m16n8k8.row.col.f32.tf32.tf32.f32 "
        "{%0,%1,%2,%3}, {%4,%5,%6,%7}, {%8,%9}, {%0,%1,%2,%3};"
        : "+f"(d.x), "+f"(d.y), "+f"(d.z), "+f"(d.w)
        : "r"(__float_as_uint(a.x)), "r"(__float_as_uint(a.y)),
          "r"(__float_as_uint(a.z)), "r"(__float_as_uint(a.w)),
          "r"(__float_as_uint(b.x)), "r"(__float_as_uint(b.y)));
}

__device__ __forceinline__ void cpa16(uint32_t dst, const float* src) {
    asm volatile("cp.async.cg.shared.global [%0], [%1], 16;" :: "r"(dst), "l"(src));
}

// ---------------------------------------------------------------------------
// K=1024 GEMM, cp.async 2-stage, 128x128 tile, BK=16, **512 threads**
// (16 warps, 4m x 4n; warp job 32x32 = 2 m16 x 4 n8). Row-major smem,
// stride 20 (conflict-free). Consume-time tf32 (RNA). 40 KB static smem.
// MODE 0: scatter to [B,H,S,HD] (dst 0/1/2 = Q/K/V);  MODE 1: row-major out.
// ---------------------------------------------------------------------------
template <int MODE>
__global__ __launch_bounds__(512) void k_gemm1024(
    const float* __restrict__ Ain, const float* __restrict__ W,
    const float* __restrict__ bias, float* __restrict__ out,
    int dst, float scale)
{
    __shared__ float As[2][128 * 20];
    __shared__ float Ws[2][128 * 20];

    const float* A = (MODE == 1) ? g_ctx : Ain;
    float* C = (MODE == 1) ? out : ((dst == 0) ? g_Q : (dst == 1) ? g_K : g_V);

    const int row0 = blockIdx.y * 128, col0 = blockIdx.x * 128;
    const int t = threadIdx.x, wid = t >> 5, lane = t & 31;
    const int grp = lane >> 2, tig = lane & 3;
    const int wm = (wid >> 2) * 32, wn = (wid & 3) * 32;
    const int sr = t >> 2, sc4 = (t & 3) * 4;

    const float* Ap = A + (long)(row0 + sr) * Dc + sc4;
    const float* Wp = W + (long)(col0 + sr) * Dc + sc4;

    const uint32_t aSm = (uint32_t)__cvta_generic_to_shared(&As[0][sr * 20 + sc4]);
    const uint32_t wSm = (uint32_t)__cvta_generic_to_shared(&Ws[0][sr * 20 + sc4]);
    constexpr uint32_t BUFB = 128 * 20 * 4;

    float4 acc0[4], acc1[4];
#pragma unroll
    for (int i = 0; i < 4; i++) {
        acc0[i] = make_float4(0.f, 0.f, 0.f, 0.f);
        acc1[i] = make_float4(0.f, 0.f, 0.f, 0.f);
    }

    // prologue: stage k-chunk 0 (one 16B cp.async per thread per array)
    cpa16(aSm, Ap);
    cpa16(wSm, Wp);
    asm volatile("cp.async.commit_group;");

    for (int kt = 0; kt < 64; kt++) {
        if (kt < 63) {
            const int k0 = (kt + 1) * 16;
            const uint32_t b = ((kt + 1) & 1) * BUFB;
            cpa16(aSm + b, Ap + k0);
            cpa16(wSm + b, Wp + k0);
            asm volatile("cp.async.commit_group;");
            asm volatile("cp.async.wait_group 1;");
        } else {
            asm volatile("cp.async.wait_group 0;");
        }
        __syncthreads();

        const float* Ab = As[kt & 1];
        const float* Wb = Ws[kt & 1];
#pragma unroll
        for (int kb = 0; kb < 2; kb++) {
            const int ko = kb * 8 + tig;
            float4 fa0 = make_float4(stf(Ab[(wm + grp     ) * 20 + ko]),
                                     stf(Ab[(wm + grp + 8 ) * 20 + ko]),
                                     stf(Ab[(wm + grp     ) * 20 + ko + 4]),
                                     stf(Ab[(wm + grp + 8 ) * 20 + ko + 4]));
            float4 fa1 = make_float4(stf(Ab[(wm + 16 + grp    ) * 20 + ko]),
                                     stf(Ab[(wm + 16 + grp + 8) * 20 + ko]),
                                     stf(Ab[(wm + 16 + grp    ) * 20 + ko + 4]),
                                     stf(Ab[(wm + 16 + grp + 8) * 20 + ko + 4]));
#pragma unroll
            for (int j = 0; j < 4; j++) {
                float2 fb = make_float2(stf(Wb[(wn + j * 8 + grp) * 20 + ko]),
                                        stf(Wb[(wn + j * 8 + grp) * 20 + ko + 4]));
                mma8(acc0[j], fa0, fb);
                mma8(acc1[j], fa1, fb);
            }
        }
        __syncthreads();
    }

#pragma unroll
    for (int mt = 0; mt < 2; mt++) {
#pragma unroll
        for (int j = 0; j < 4; j++) {
            float4 c = mt ? acc1[j] : acc0[j];
            const int row = row0 + wm + mt * 16 + grp;
            const int col = col0 + wn + j * 8 + tig * 2;
            const float bx0 = bias[col], bx1 = bias[col + 1];
            if (MODE == 1) {
                *(float2*)&C[(long)row * Dc + col] =
                    make_float2(c.x + bx0, c.y + bx1);
                *(float2*)&C[(long)(row + 8) * Dc + col] =
                    make_float2(c.z + bx0, c.w + bx1);
            } else {
                const int h = col >> 6, hd = col & 63;
                {
                    const int bb = row >> 11, s = row & 2047;
                    *(float2*)&C[(((long)(bb * Hc + h)) * Sc + s) * HDc + hd] =
                        make_float2((c.x + bx0) * scale, (c.y + bx1) * scale);
                }
                {
                    const int r2 = row + 8;
                    const int bb = r2 >> 11, s = r2 & 2047;
                    *(float2*)&C[(((long)(bb * Hc + h)) * Sc + s) * HDc + hd] =
                        make_float2((c.z + bx0) * scale, (c.w + bx1) * scale);
                }
            }
        }
    }
}

// ---------------------------------------------------------------------------
// Fused causal attention, SINGLE PASS, 512 threads (16 warps), with
// register prefetch of K/V (tile kt+1 loaded after the S-epilogue, consumed
// at next staging — latency hidden by PV-mma + barrier). No zero-fill here
// (k_rescale owns the upper triangle, per measured-best R8 arrangement).
// Warp S-tile 32x32, O-tile 32x16. Fragment-major smem (~170 KB).
// ---------------------------------------------------------------------------
__global__ __launch_bounds__(512) void k_attn_fused(float* __restrict__ ATT)
{
    extern __shared__ float smf[];
    float* QsF  = smf;                 // 8448  [mt8][kb8]*132
    float* KsF  = smf + 8448;          // 8704  [nt16][kb8]*68
    float* VsF  = KsF + 8704;          // 8704  [kb16][nt8]*68
    float* PsF  = VsF + 8704;          // 16896 [mt8][kb16]*132
    float* red  = PsF + 16896;         // 512
    float* invl = red + 512;           // 128

    const int bh = blockIdx.z;
    const int qt = (int)gridDim.x - 1 - (int)blockIdx.x;   // heavy tiles first
    const int q0 = qt * 128;
    const float* Qg = g_Q + (long)bh * Sc * HDc;
    const float* Kg = g_K + (long)bh * Sc * HDc;
    const float* Vg = g_V + (long)bh * Sc * HDc;
    float* Ab = ATT + (long)bh * Sc * Sc;

    const int t = threadIdx.x, wid = t >> 5, lane = t & 31;
    const int grp = lane >> 2, tig = lane & 3;
    const int wm   = (wid >> 2) * 32;
    const int mt0  = (wid >> 2) * 2;
    const int wqS  = wid & 3;
    const int ntS0 = wqS * 4;
    const int ntO0 = (wid & 3) * 2;

    // prologue: prefetch K/V tile 0 into registers (overlaps Q staging)
    float4 kR[4], vR[4];
#pragma unroll
    for (int i = 0; i < 4; i++) {
        const int row = (t + i * 512) >> 4;
        const int c4  = ((t + i * 512) & 15) * 4;
        kR[i] = *(const float4*)(Kg + (long)row * HDc + c4);
        vR[i] = *(const float4*)(Vg + (long)row * HDc + c4);
    }

    // Stage Q tile (128x64) as A-fragments
#pragma unroll
    for (int i = 0; i < 4; i++) {
        const int idx = t + i * 512;
        const int row = idx >> 4, c4 = (idx & 15) * 4;
        float4 v = *(const float4*)(Qg + (long)(q0 + row) * HDc + c4);
        const int kb = c4 >> 3, k4 = (c4 >> 2) & 1;
        const int mt = row >> 4, m = row & 15;
        const int b = (mt * 8 + kb) * 132 + (m & 7) * 16 + k4 * 2 + ((m >> 3) & 1);
        QsF[b + 0] = stf(v.x); QsF[b + 4]  = stf(v.y);
        QsF[b + 8] = stf(v.z); QsF[b + 12] = stf(v.w);
    }

    float ps00 = 0.f, ps01 = 0.f, ps10 = 0.f, ps11 = 0.f;
    float4 o0[2], o1[2];
#pragma unroll
    for (int i = 0; i < 2; i++) {
        o0[i] = make_float4(0.f, 0.f, 0.f, 0.f);
        o1[i] = make_float4(0.f, 0.f, 0.f, 0.f);
    }

    for (int kt = 0; kt <= qt; kt++) {
        __syncthreads();   // prev PV done (and Q staging / prologue first iter)

        // stage K/V from prefetch registers (formatted, tf32)
#pragma unroll
        for (int i = 0; i < 4; i++) {
            const int idx = t + i * 512;
            const int row = idx >> 4, c4 = (idx & 15) * 4;
            float4 kv = kR[i];
            {
                const int kb = c4 >> 3, k4 = (c4 >> 2) & 1;
                const int nt = row >> 3, n = row & 7;
                const int b = (nt * 8 + kb) * 68 + n * 8 + k4;
                KsF[b + 0] = stf(kv.x); KsF[b + 2] = stf(kv.y);
                KsF[b + 4] = stf(kv.z); KsF[b + 6] = stf(kv.w);
            }
            float4 vv = vR[i];
            {
                const int kbv = row >> 3, kk = row & 7;
                const int nt = c4 >> 3, nb = c4 & 7;
                const int b = (kbv * 8 + nt) * 68 + nb * 8 + (kk & 3) * 2 + ((kk >> 2) & 1);
                VsF[b + 0]  = stf(vv.x); VsF[b + 8]  = stf(vv.y);
                VsF[b + 16] = stf(vv.z); VsF[b + 24] = stf(vv.w);
            }
        }
        __syncthreads();

        // S = Q @ K^T
        float4 acc0[4], acc1[4];
#pragma unroll
        for (int i = 0; i < 4; i++) {
            acc0[i] = make_float4(0.f, 0.f, 0.f, 0.f);
            acc1[i] = make_float4(0.f, 0.f, 0.f, 0.f);
        }
#pragma unroll
        for (int kb = 0; kb < 8; kb++) {
            float4 fa0 = *(const float4*)&QsF[((mt0 + 0) * 8 + kb) * 132 + lane * 4];
            float4 fa1 = *(const float4*)&QsF[((mt0 + 1) * 8 + kb) * 132 + lane * 4];
#pragma unroll
            for (int j = 0; j < 4; j++) {
                float2 fb = *(const float2*)&KsF[((ntS0 + j) * 8 + kb) * 68 + lane * 2];
                mma8(acc0[j], fa0, fb);
                mma8(acc1[j], fa1, fb);
            }
        }

        // exp (unnormalized), mask, write ATT, stage P frags, accumulate sums
        const bool diag = (kt == qt);
#pragma unroll
        for (int mt = 0; mt < 2; mt++) {
            const int r = wm + mt * 16 + grp;
            const int mtg = mt0 + mt;
#pragma unroll
            for (int j = 0; j < 4; j++) {
                float4 c = mt ? acc1[j] : acc0[j];
                const int cc = wqS * 32 + j * 8 + tig * 2;
                float ex = (!diag || cc     <= r    ) ? __expf(c.x) : 0.f;
                float ey = (!diag || cc + 1 <= r    ) ? __expf(c.y) : 0.f;
                float ez = (!diag || cc     <= r + 8) ? __expf(c.z) : 0.f;
                float ew = (!diag || cc + 1 <= r + 8) ? __expf(c.w) : 0.f;
                if (mt == 0) { ps00 += ex + ey; ps01 += ez + ew; }
                else         { ps10 += ex + ey; ps11 += ez + ew; }
                const long gr = (long)(q0 + r) * Sc + kt * 128 + cc;
                *(float2*)&Ab[gr]          = make_float2(ex, ey);
                *(float2*)&Ab[gr + 8 * Sc] = make_float2(ez, ew);
                const int kbp = wqS * 4 + j;
                const int k = tig * 2;
                const int o = (mtg * 16 + kbp) * 132 + grp * 16 + (k & 3) * 4 + (k >> 2) * 2;
                *(float2*)&PsF[o]     = make_float2(stf(ex), stf(ez));
                *(float2*)&PsF[o + 4] = make_float2(stf(ey), stf(ew));
            }
        }

        // prefetch K/V tile kt+1 (latency hidden by barrier + PV-mma)
        if (kt < qt) {
#pragma unroll
            for (int i = 0; i < 4; i++) {
                const int row = (t + i * 512) >> 4;
                const int c4  = ((t + i * 512) & 15) * 4;
                kR[i] = *(const float4*)(Kg + (long)((kt + 1) * 128 + row) * HDc + c4);
                vR[i] = *(const float4*)(Vg + (long)((kt + 1) * 128 + row) * HDc + c4);
            }
        }
        __syncthreads();

        // O += P @ V
#pragma unroll
        for (int kb = 0; kb < 16; kb++) {
            float4 pa0 = *(const float4*)&PsF[((mt0 + 0) * 16 + kb) * 132 + lane * 4];
            float4 pa1 = *(const float4*)&PsF[((mt0 + 1) * 16 + kb) * 132 + lane * 4];
#pragma unroll
            for (int j = 0; j < 2; j++) {
                float2 vb = *(const float2*)&VsF[(kb * 8 + ntO0 + j) * 68 + lane * 2];
                mma8(o0[j], pa0, vb);
                mma8(o1[j], pa1, vb);
            }
        }
    }

    // row-sum reduction -> invl
#pragma unroll
    for (int o = 1; o <= 2; o <<= 1) {
        ps00 += __shfl_xor_sync(0xffffffffu, ps00, o);
        ps01 += __shfl_xor_sync(0xffffffffu, ps01, o);
        ps10 += __shfl_xor_sync(0xffffffffu, ps10, o);
        ps11 += __shfl_xor_sync(0xffffffffu, ps11, o);
    }
    if (tig == 0) {
        float* rb = red + wqS * 128;
        rb[wm + grp]          = ps00;
        rb[wm + grp + 8]      = ps01;
        rb[wm + 16 + grp]     = ps10;
        rb[wm + 16 + grp + 8] = ps11;
    }
    __syncthreads();
    if (t < 128) {
        const float il = 1.0f / (red[t] + red[128 + t] + red[256 + t] + red[384 + t]);
        invl[t] = il;
        g_invl[(long)bh * Sc + q0 + t] = il;
    }
    __syncthreads();

    // epilogue: ctx = O * invl
    const int bb = bh >> 4, h = bh & 15;
#pragma unroll
    for (int mt = 0; mt < 2; mt++) {
        const int r = wm + mt * 16 + grp;
        const float il0 = invl[r], il1 = invl[r + 8];
#pragma unroll
        for (int j = 0; j < 2; j++) {
            float4 c = mt ? o1[j] : o0[j];
            const int gq  = q0 + r;
            const int col = (wid & 3) * 16 + j * 8 + tig * 2;
            *(float2*)&g_ctx[((long)bb * Sc + gq) * Dc + h * HDc + col] =
                make_float2(c.x * il0, c.y * il0);
            *(float2*)&g_ctx[((long)bb * Sc + gq + 8) * Dc + h * HDc + col] =
                make_float2(c.z * il1, c.w * il1);
        }
    }
}

// ---------------------------------------------------------------------------
// Rescale + zero-fill: one block per (bh,q) row of attn (R8 arrangement).
// Scales cols [0, ceil128(q+1)) by invl, zeros cols [ceil128(q+1), Sc).
// ---------------------------------------------------------------------------
__global__ __launch_bounds__(256) void k_rescale(float* __restrict__ ATT)
{
    const long row = blockIdx.x;
    const int  q   = (int)(row & (Sc - 1));
    const float il = g_invl[row];
    float* p = ATT + row * Sc;
    const int nc = (((q >> 7) + 1) << 7);   // cols written by fused kernel
    const int t4 = threadIdx.x * 4;

    for (int i = t4; i < nc; i += 1024) {
        float4 v = *(float4*)&p[i];
        v.x *= il; v.y *= il; v.z *= il; v.w *= il;
        *(float4*)&p[i] = v;
    }
    for (int i = nc + t4; i < Sc; i += 1024)
        *(float4*)&p[i] = make_float4(0.f, 0.f, 0.f, 0.f);
}

// ---------------------------------------------------------------------------
// kernel_launch
// Inputs: 0 query, 1 key, 2 value, 3 mask, 4 Wq, 5 bq, 6 Wk, 7 bk,
//         8 Wv, 9 bv, 10 Wo, 11 bo
// Output tuple (output, attn): out[0:B*S*D], attn at out + B*S*D.
// ---------------------------------------------------------------------------
extern "C" void kernel_launch(void* const* d_in, const int* in_sizes, int n_in,
                              void* d_out, int out_size)
{
    const float* query = (const float*)d_in[0];
    const float* key_  = (const float*)d_in[1];
    const float* value = (const float*)d_in[2];
    const float* Wq = (const float*)d_in[4];
    const float* bq = (const float*)d_in[5];
    const float* Wk = (const float*)d_in[6];
    const float* bk = (const float*)d_in[7];
    const float* Wv = (const float*)d_in[8];
    const float* bv = (const float*)d_in[9];
    const float* Wo = (const float*)d_in[10];
    const float* bo = (const float*)d_in[11];
    float* out = (float*)d_out;

    float* ATT = out + OUT_ELEMS;   // attn region of the output tuple

    constexpr int FUSED_SMEM = (8448 + 8704 + 8704 + 16896 + 512 + 128) * 4;
    cudaFuncSetAttribute(k_attn_fused,
                         cudaFuncAttributeMaxDynamicSharedMemorySize, FUSED_SMEM);

    const dim3 blk512(512);

    k_gemm1024<0><<<dim3(Dc / 128, Nrows / 128), blk512>>>(query, Wq, bq, nullptr, 0, 0.125f);
    k_gemm1024<0><<<dim3(Dc / 128, Nrows / 128), blk512>>>(key_,  Wk, bk, nullptr, 1, 1.0f);
    k_gemm1024<0><<<dim3(Dc / 128, Nrows / 128), blk512>>>(value, Wv, bv, nullptr, 2, 1.0f);

    k_attn_fused<<<dim3(Sc / 128, 1, Bc * Hc), blk512, FUSED_SMEM>>>(ATT);

    k_rescale<<<dim3(Bc * Hc * Sc), dim3(256)>>>(ATT);

    k_gemm1024<1><<<dim3(Dc / 128, Nrows / 128), blk512>>>(nullptr, Wo, bo, out, 0, 1.0f);
}

// round 15
// speedup vs baseline: 1.2279x; 1.0025x over previous
#include <cuda_runtime.h>
#include <cstdint>

// Problem constants
constexpr int Bc  = 2;
constexpr int Sc  = 2048;
constexpr int Dc  = 1024;
constexpr int Hc  = 16;
constexpr int HDc = 64;
constexpr int Nrows = Bc * Sc;                       // 4096
constexpr long OUT_ELEMS = (long)Bc * Sc * Dc;       // 4,194,304

// Scratch (device globals; sanctioned mechanism).
__device__ __align__(16) float g_Q[Bc * Hc * Sc * HDc];    // [B,H,S,HD], pre-scaled by 1/8
__device__ __align__(16) float g_K[Bc * Hc * Sc * HDc];
__device__ __align__(16) float g_V[Bc * Hc * Sc * HDc];
__device__ __align__(16) float g_ctx[(long)Nrows * Dc];    // [B*S, D]
__device__ __align__(16) float g_invl[Bc * Hc * Sc];       // 1/rowsum per (bh,q)

// ---------------------------------------------------------------------------
// helpers
// ---------------------------------------------------------------------------
__device__ __forceinline__ float stf(float x) {
    uint32_t r;
    asm("cvt.rna.tf32.f32 %0, %1;" : "=r"(r) : "f"(x));
    return __uint_as_float(r);
}

__device__ __forceinline__ void mma8(float4& d, float4 a, float2 b)
{
    asm volatile(
        "mma.sync.aligned.m16n8k8.row.col.f32.tf32.tf32.f32 "
        "{%0,%1,%2,%3}, {%4,%5,%6,%7}, {%8,%9}, {%0,%1,%2,%3};"
        : "+f"(d.x), "+f"(d.y), "+f"(d.z), "+f"(d.w)
        : "r"(__float_as_uint(a.x)), "r"(__float_as_uint(a.y)),
          "r"(__float_as_uint(a.z)), "r"(__float_as_uint(a.w)),
          "r"(__float_as_uint(b.x)), "r"(__float_as_uint(b.y)));
}

__device__ __forceinline__ void cpa16(uint32_t dst, const float* src) {
    asm volatile("cp.async.cg.shared.global [%0], [%1], 16;" :: "r"(dst), "l"(src));
}

// ---------------------------------------------------------------------------
// K=1024 GEMM, cp.async 2-stage, 128x128 tile, BK=16, **512 threads**
// (16 warps, 4m x 4n; warp job 32x32 = 2 m16 x 4 n8). Row-major smem,
// stride 20 (conflict-free). Consume-time tf32 (RNA). 40 KB static smem.
// MODE 0: scatter to [B,H,S,HD] (dst 0/1/2 = Q/K/V);  MODE 1: row-major out.
// ---------------------------------------------------------------------------
template <int MODE>
__global__ __launch_bounds__(512) void k_gemm1024(
    const float* __restrict__ Ain, const float* __restrict__ W,
    const float* __restrict__ bias, float* __restrict__ out,
    int dst, float scale)
{
    __shared__ float As[2][128 * 20];
    __shared__ float Ws[2][128 * 20];

    const float* A = (MODE == 1) ? g_ctx : Ain;
    float* C = (MODE == 1) ? out : ((dst == 0) ? g_Q : (dst == 1) ? g_K : g_V);

    const int row0 = blockIdx.y * 128, col0 = blockIdx.x * 128;
    const int t = threadIdx.x, wid = t >> 5, lane = t & 31;
    const int grp = lane >> 2, tig = lane & 3;
    const int wm = (wid >> 2) * 32, wn = (wid & 3) * 32;
    const int sr = t >> 2, sc4 = (t & 3) * 4;

    const float* Ap = A + (long)(row0 + sr) * Dc + sc4;
    const float* Wp = W + (long)(col0 + sr) * Dc + sc4;

    const uint32_t aSm = (uint32_t)__cvta_generic_to_shared(&As[0][sr * 20 + sc4]);
    const uint32_t wSm = (uint32_t)__cvta_generic_to_shared(&Ws[0][sr * 20 + sc4]);
    constexpr uint32_t BUFB = 128 * 20 * 4;

    float4 acc0[4], acc1[4];
#pragma unroll
    for (int i = 0; i < 4; i++) {
        acc0[i] = make_float4(0.f, 0.f, 0.f, 0.f);
        acc1[i] = make_float4(0.f, 0.f, 0.f, 0.f);
    }

    // prologue: stage k-chunk 0 (one 16B cp.async per thread per array)
    cpa16(aSm, Ap);
    cpa16(wSm, Wp);
    asm volatile("cp.async.commit_group;");

    for (int kt = 0; kt < 64; kt++) {
        if (kt < 63) {
            const int k0 = (kt + 1) * 16;
            const uint32_t b = ((kt + 1) & 1) * BUFB;
            cpa16(aSm + b, Ap + k0);
            cpa16(wSm + b, Wp + k0);
            asm volatile("cp.async.commit_group;");
            asm volatile("cp.async.wait_group 1;");
        } else {
            asm volatile("cp.async.wait_group 0;");
        }
        __syncthreads();

        const float* Ab = As[kt & 1];
        const float* Wb = Ws[kt & 1];
#pragma unroll
        for (int kb = 0; kb < 2; kb++) {
            const int ko = kb * 8 + tig;
            float4 fa0 = make_float4(stf(Ab[(wm + grp     ) * 20 + ko]),
                                     stf(Ab[(wm + grp + 8 ) * 20 + ko]),
                                     stf(Ab[(wm + grp     ) * 20 + ko + 4]),
                                     stf(Ab[(wm + grp + 8 ) * 20 + ko + 4]));
            float4 fa1 = make_float4(stf(Ab[(wm + 16 + grp    ) * 20 + ko]),
                                     stf(Ab[(wm + 16 + grp + 8) * 20 + ko]),
                                     stf(Ab[(wm + 16 + grp    ) * 20 + ko + 4]),
                                     stf(Ab[(wm + 16 + grp + 8) * 20 + ko + 4]));
#pragma unroll
            for (int j = 0; j < 4; j++) {
                float2 fb = make_float2(stf(Wb[(wn + j * 8 + grp) * 20 + ko]),
                                        stf(Wb[(wn + j * 8 + grp) * 20 + ko + 4]));
                mma8(acc0[j], fa0, fb);
                mma8(acc1[j], fa1, fb);
            }
        }
        __syncthreads();
    }

#pragma unroll
    for (int mt = 0; mt < 2; mt++) {
#pragma unroll
        for (int j = 0; j < 4; j++) {
            float4 c = mt ? acc1[j] : acc0[j];
            const int row = row0 + wm + mt * 16 + grp;
            const int col = col0 + wn + j * 8 + tig * 2;
            const float bx0 = bias[col], bx1 = bias[col + 1];
            if (MODE == 1) {
                *(float2*)&C[(long)row * Dc + col] =
                    make_float2(c.x + bx0, c.y + bx1);
                *(float2*)&C[(long)(row + 8) * Dc + col] =
                    make_float2(c.z + bx0, c.w + bx1);
            } else {
                const int h = col >> 6, hd = col & 63;
                {
                    const int bb = row >> 11, s = row & 2047;
                    *(float2*)&C[(((long)(bb * Hc + h)) * Sc + s) * HDc + hd] =
                        make_float2((c.x + bx0) * scale, (c.y + bx1) * scale);
                }
                {
                    const int r2 = row + 8;
                    const int bb = r2 >> 11, s = r2 & 2047;
                    *(float2*)&C[(((long)(bb * Hc + h)) * Sc + s) * HDc + hd] =
                        make_float2((c.z + bx0) * scale, (c.w + bx1) * scale);
                }
            }
        }
    }
}

// ---------------------------------------------------------------------------
// Fused causal attention, SINGLE PASS, 512 threads (16 warps), with
// register prefetch of K/V (tile kt+1 loaded after the S-epilogue, consumed
// at next staging — latency hidden by PV-mma + barrier). No zero-fill here
// (k_rescale owns the upper triangle, per measured-best R8 arrangement).
// Warp S-tile 32x32, O-tile 32x16. Fragment-major smem (~170 KB).
// ---------------------------------------------------------------------------
__global__ __launch_bounds__(512) void k_attn_fused(float* __restrict__ ATT)
{
    extern __shared__ float smf[];
    float* QsF  = smf;                 // 8448  [mt8][kb8]*132
    float* KsF  = smf + 8448;          // 8704  [nt16][kb8]*68
    float* VsF  = KsF + 8704;          // 8704  [kb16][nt8]*68
    float* PsF  = VsF + 8704;          // 16896 [mt8][kb16]*132
    float* red  = PsF + 16896;         // 512
    float* invl = red + 512;           // 128

    const int bh = blockIdx.z;
    const int qt = (int)gridDim.x - 1 - (int)blockIdx.x;   // heavy tiles first
    const int q0 = qt * 128;
    const float* Qg = g_Q + (long)bh * Sc * HDc;
    const float* Kg = g_K + (long)bh * Sc * HDc;
    const float* Vg = g_V + (long)bh * Sc * HDc;
    float* Ab = ATT + (long)bh * Sc * Sc;

    const int t = threadIdx.x, wid = t >> 5, lane = t & 31;
    const int grp = lane >> 2, tig = lane & 3;
    const int wm   = (wid >> 2) * 32;
    const int mt0  = (wid >> 2) * 2;
    const int wqS  = wid & 3;
    const int ntS0 = wqS * 4;
    const int ntO0 = (wid & 3) * 2;

    // prologue: prefetch K/V tile 0 into registers (overlaps Q staging)
    float4 kR[4], vR[4];
#pragma unroll
    for (int i = 0; i < 4; i++) {
        const int row = (t + i * 512) >> 4;
        const int c4  = ((t + i * 512) & 15) * 4;
        kR[i] = *(const float4*)(Kg + (long)row * HDc + c4);
        vR[i] = *(const float4*)(Vg + (long)row * HDc + c4);
    }

    // Stage Q tile (128x64) as A-fragments
#pragma unroll
    for (int i = 0; i < 4; i++) {
        const int idx = t + i * 512;
        const int row = idx >> 4, c4 = (idx & 15) * 4;
        float4 v = *(const float4*)(Qg + (long)(q0 + row) * HDc + c4);
        const int kb = c4 >> 3, k4 = (c4 >> 2) & 1;
        const int mt = row >> 4, m = row & 15;
        const int b = (mt * 8 + kb) * 132 + (m & 7) * 16 + k4 * 2 + ((m >> 3) & 1);
        QsF[b + 0] = stf(v.x); QsF[b + 4]  = stf(v.y);
        QsF[b + 8] = stf(v.z); QsF[b + 12] = stf(v.w);
    }

    float ps00 = 0.f, ps01 = 0.f, ps10 = 0.f, ps11 = 0.f;
    float4 o0[2], o1[2];
#pragma unroll
    for (int i = 0; i < 2; i++) {
        o0[i] = make_float4(0.f, 0.f, 0.f, 0.f);
        o1[i] = make_float4(0.f, 0.f, 0.f, 0.f);
    }

    for (int kt = 0; kt <= qt; kt++) {
        __syncthreads();   // prev PV done (and Q staging / prologue first iter)

        // stage K/V from prefetch registers (formatted, tf32)
#pragma unroll
        for (int i = 0; i < 4; i++) {
            const int idx = t + i * 512;
            const int row = idx >> 4, c4 = (idx & 15) * 4;
            float4 kv = kR[i];
            {
                const int kb = c4 >> 3, k4 = (c4 >> 2) & 1;
                const int nt = row >> 3, n = row & 7;
                const int b = (nt * 8 + kb) * 68 + n * 8 + k4;
                KsF[b + 0] = stf(kv.x); KsF[b + 2] = stf(kv.y);
                KsF[b + 4] = stf(kv.z); KsF[b + 6] = stf(kv.w);
            }
            float4 vv = vR[i];
            {
                const int kbv = row >> 3, kk = row & 7;
                const int nt = c4 >> 3, nb = c4 & 7;
                const int b = (kbv * 8 + nt) * 68 + nb * 8 + (kk & 3) * 2 + ((kk >> 2) & 1);
                VsF[b + 0]  = stf(vv.x); VsF[b + 8]  = stf(vv.y);
                VsF[b + 16] = stf(vv.z); VsF[b + 24] = stf(vv.w);
            }
        }
        __syncthreads();

        // S = Q @ K^T
        float4 acc0[4], acc1[4];
#pragma unroll
        for (int i = 0; i < 4; i++) {
            acc0[i] = make_float4(0.f, 0.f, 0.f, 0.f);
            acc1[i] = make_float4(0.f, 0.f, 0.f, 0.f);
        }
#pragma unroll
        for (int kb = 0; kb < 8; kb++) {
            float4 fa0 = *(const float4*)&QsF[((mt0 + 0) * 8 + kb) * 132 + lane * 4];
            float4 fa1 = *(const float4*)&QsF[((mt0 + 1) * 8 + kb) * 132 + lane * 4];
#pragma unroll
            for (int j = 0; j < 4; j++) {
                float2 fb = *(const float2*)&KsF[((ntS0 + j) * 8 + kb) * 68 + lane * 2];
                mma8(acc0[j], fa0, fb);
                mma8(acc1[j], fa1, fb);
            }
        }

        // exp (unnormalized), mask, write ATT, stage P frags, accumulate sums
        const bool diag = (kt == qt);
#pragma unroll
        for (int mt = 0; mt < 2; mt++) {
            const int r = wm + mt * 16 + grp;
            const int mtg = mt0 + mt;
#pragma unroll
            for (int j = 0; j < 4; j++) {
                float4 c = mt ? acc1[j] : acc0[j];
                const int cc = wqS * 32 + j * 8 + tig * 2;
                float ex = (!diag || cc     <= r    ) ? __expf(c.x) : 0.f;
                float ey = (!diag || cc + 1 <= r    ) ? __expf(c.y) : 0.f;
                float ez = (!diag || cc     <= r + 8) ? __expf(c.z) : 0.f;
                float ew = (!diag || cc + 1 <= r + 8) ? __expf(c.w) : 0.f;
                if (mt == 0) { ps00 += ex + ey; ps01 += ez + ew; }
                else         { ps10 += ex + ey; ps11 += ez + ew; }
                const long gr = (long)(q0 + r) * Sc + kt * 128 + cc;
                *(float2*)&Ab[gr]          = make_float2(ex, ey);
                *(float2*)&Ab[gr + 8 * Sc] = make_float2(ez, ew);
                const int kbp = wqS * 4 + j;
                const int k = tig * 2;
                const int o = (mtg * 16 + kbp) * 132 + grp * 16 + (k & 3) * 4 + (k >> 2) * 2;
                *(float2*)&PsF[o]     = make_float2(stf(ex), stf(ez));
                *(float2*)&PsF[o + 4] = make_float2(stf(ey), stf(ew));
            }
        }

        // prefetch K/V tile kt+1 (latency hidden by barrier + PV-mma)
        if (kt < qt) {
#pragma unroll
            for (int i = 0; i < 4; i++) {
                const int row = (t + i * 512) >> 4;
                const int c4  = ((t + i * 512) & 15) * 4;
                kR[i] = *(const float4*)(Kg + (long)((kt + 1) * 128 + row) * HDc + c4);
                vR[i] = *(const float4*)(Vg + (long)((kt + 1) * 128 + row) * HDc + c4);
            }
        }
        __syncthreads();

        // O += P @ V
#pragma unroll
        for (int kb = 0; kb < 16; kb++) {
            float4 pa0 = *(const float4*)&PsF[((mt0 + 0) * 16 + kb) * 132 + lane * 4];
            float4 pa1 = *(const float4*)&PsF[((mt0 + 1) * 16 + kb) * 132 + lane * 4];
#pragma unroll
            for (int j = 0; j < 2; j++) {
                float2 vb = *(const float2*)&VsF[(kb * 8 + ntO0 + j) * 68 + lane * 2];
                mma8(o0[j], pa0, vb);
                mma8(o1[j], pa1, vb);
            }
        }
    }

    // row-sum reduction -> invl
#pragma unroll
    for (int o = 1; o <= 2; o <<= 1) {
        ps00 += __shfl_xor_sync(0xffffffffu, ps00, o);
        ps01 += __shfl_xor_sync(0xffffffffu, ps01, o);
        ps10 += __shfl_xor_sync(0xffffffffu, ps10, o);
        ps11 += __shfl_xor_sync(0xffffffffu, ps11, o);
    }
    if (tig == 0) {
        float* rb = red + wqS * 128;
        rb[wm + grp]          = ps00;
        rb[wm + grp + 8]      = ps01;
        rb[wm + 16 + grp]     = ps10;
        rb[wm + 16 + grp + 8] = ps11;
    }
    __syncthreads();
    if (t < 128) {
        const float il = 1.0f / (red[t] + red[128 + t] + red[256 + t] + red[384 + t]);
        invl[t] = il;
        g_invl[(long)bh * Sc + q0 + t] = il;
    }
    __syncthreads();

    // epilogue: ctx = O * invl
    const int bb = bh >> 4, h = bh & 15;
#pragma unroll
    for (int mt = 0; mt < 2; mt++) {
        const int r = wm + mt * 16 + grp;
        const float il0 = invl[r], il1 = invl[r + 8];
#pragma unroll
        for (int j = 0; j < 2; j++) {
            float4 c = mt ? o1[j] : o0[j];
            const int gq  = q0 + r;
            const int col = (wid & 3) * 16 + j * 8 + tig * 2;
            *(float2*)&g_ctx[((long)bb * Sc + gq) * Dc + h * HDc + col] =
                make_float2(c.x * il0, c.y * il0);
            *(float2*)&g_ctx[((long)bb * Sc + gq + 8) * Dc + h * HDc + col] =
                make_float2(c.z * il1, c.w * il1);
        }
    }
}

// ---------------------------------------------------------------------------
// Rescale + zero-fill: one block per (bh,q) row of attn (R8 arrangement).
// Scales cols [0, ceil128(q+1)) by invl, zeros cols [ceil128(q+1), Sc).
// ---------------------------------------------------------------------------
__global__ __launch_bounds__(256) void k_rescale(float* __restrict__ ATT)
{
    const long row = blockIdx.x;
    const int  q   = (int)(row & (Sc - 1));
    const float il = g_invl[row];
    float* p = ATT + row * Sc;
    const int nc = (((q >> 7) + 1) << 7);   // cols written by fused kernel
    const int t4 = threadIdx.x * 4;

    for (int i = t4; i < nc; i += 1024) {
        float4 v = *(float4*)&p[i];
        v.x *= il; v.y *= il; v.z *= il; v.w *= il;
        *(float4*)&p[i] = v;
    }
    for (int i = nc + t4; i < Sc; i += 1024)
        *(float4*)&p[i] = make_float4(0.f, 0.f, 0.f, 0.f);
}

// ---------------------------------------------------------------------------
// kernel_launch
// Inputs: 0 query, 1 key, 2 value, 3 mask, 4 Wq, 5 bq, 6 Wk, 7 bk,
//         8 Wv, 9 bv, 10 Wo, 11 bo
// Output tuple (output, attn): out[0:B*S*D], attn at out + B*S*D.
// ---------------------------------------------------------------------------
extern "C" void kernel_launch(void* const* d_in, const int* in_sizes, int n_in,
                              void* d_out, int out_size)
{
    const float* query = (const float*)d_in[0];
    const float* key_  = (const float*)d_in[1];
    const float* value = (const float*)d_in[2];
    const float* Wq = (const float*)d_in[4];
    const float* bq = (const float*)d_in[5];
    const float* Wk = (const float*)d_in[6];
    const float* bk = (const float*)d_in[7];
    const float* Wv = (const float*)d_in[8];
    const float* bv = (const float*)d_in[9];
    const float* Wo = (const float*)d_in[10];
    const float* bo = (const float*)d_in[11];
    float* out = (float*)d_out;

    float* ATT = out + OUT_ELEMS;   // attn region of the output tuple

    constexpr int FUSED_SMEM = (8448 + 8704 + 8704 + 16896 + 512 + 128) * 4;
    cudaFuncSetAttribute(k_attn_fused,
                         cudaFuncAttributeMaxDynamicSharedMemorySize, FUSED_SMEM);

    const dim3 blk512(512);

    k_gemm1024<0><<<dim3(Dc / 128, Nrows / 128), blk512>>>(query, Wq, bq, nullptr, 0, 0.125f);
    k_gemm1024<0><<<dim3(Dc / 128, Nrows / 128), blk512>>>(key_,  Wk, bk, nullptr, 1, 1.0f);
    k_gemm1024<0><<<dim3(Dc / 128, Nrows / 128), blk512>>>(value, Wv, bv, nullptr, 2, 1.0f);

    k_attn_fused<<<dim3(Sc / 128, 1, Bc * Hc), blk512, FUSED_SMEM>>>(ATT);

    k_rescale<<<dim3(Bc * Hc * Sc), dim3(256)>>>(ATT);

    k_gemm1024<1><<<dim3(Dc / 128, Nrows / 128), blk512>>>(nullptr, Wo, bo, out, 0, 1.0f);
}